// round 12
// baseline (speedup 1.0000x reference)
#include <cuda_runtime.h>
#include <cuda_bf16.h>
#include <cuda_fp16.h>
#include <cstdint>
#include <math.h>

#define NN 100000
#define NE 1600000
#define HF 128
#define NG 64
#define NC 10
#define SCAN_B 1024
#define NB_SCAN ((NN + SCAN_B - 1) / SCAN_B)   // 98
#define POOL_CH 256

// GEMM smem tile geometry: 128 rows x 128 bf16, padded stride 136 elems (272B)
#define TSTR 136
#define TILE_BYTES (128 * TSTR * 2)            // 34816
#define OFF_AHI 0
#define OFF_ALO (TILE_BYTES)
#define OFF_BHI (2 * TILE_BYTES)
#define OFF_BLO (3 * TILE_BYTES)
#define SMB     (4 * TILE_BYTES)               // 139264

// ---------------- scratch (static device globals; no allocation) ----------------
__device__ __half         g_h  [NN * HF];     // GEMM output per layer (fp16 rows, 256B)
__device__ __nv_bfloat16  g_ahi[NN * HF];     // activation hi part (GEMM A input)
__device__ __nv_bfloat16  g_alo[NN * HF];     // activation lo part
__device__ __nv_bfloat16  g_wthi[4 * HF * HF];// W^T hi per layer, layout [l][n][k]
__device__ __nv_bfloat16  g_wtlo[4 * HF * HF];// W^T lo per layer
__device__ float g_xB [NN * HF];              // final layer fp32 output (for pooling)
__device__ int   g_deg   [NN];
__device__ float g_dinv  [NN];
__device__ float g_invdeg[NN];
__device__ int   g_rowptr[NN + 1];
__device__ int   g_cursor[NN];
__device__ uint2 g_edge  [NE];                // packed {src, norm_bits}
__device__ int   g_bsums [128];
__device__ float g_gmax  [NG * HF];
__device__ float g_gsum  [NG * HF];
__device__ int   g_gcnt  [NG];

// ================= mma.sync / ldmatrix helpers (arch-portable PTX) =================
__device__ __forceinline__ uint32_t smem_u32(const void* p) {
    uint32_t a;
    asm("{ .reg .u64 t; cvta.to.shared.u64 t, %1; cvt.u32.u64 %0, t; }" : "=r"(a) : "l"(p));
    return a;
}
__device__ __forceinline__ void ldsm_x4(uint32_t* r, uint32_t addr) {
    asm volatile("ldmatrix.sync.aligned.m8n8.x4.shared.b16 {%0,%1,%2,%3}, [%4];"
        : "=r"(r[0]), "=r"(r[1]), "=r"(r[2]), "=r"(r[3]) : "r"(addr));
}
__device__ __forceinline__ void ldsm_x2(uint32_t* r, uint32_t addr) {
    asm volatile("ldmatrix.sync.aligned.m8n8.x2.shared.b16 {%0,%1}, [%2];"
        : "=r"(r[0]), "=r"(r[1]) : "r"(addr));
}
__device__ __forceinline__ void mma_bf16(float* c, const uint32_t* a, const uint32_t* b) {
    asm volatile("mma.sync.aligned.m16n8k16.row.col.f32.bf16.bf16.f32 "
        "{%0,%1,%2,%3}, {%4,%5,%6,%7}, {%8,%9}, {%0,%1,%2,%3};"
        : "+f"(c[0]), "+f"(c[1]), "+f"(c[2]), "+f"(c[3])
        : "r"(a[0]), "r"(a[1]), "r"(a[2]), "r"(a[3]), "r"(b[0]), "r"(b[1]));
}

// ---------------- degree / normalization ----------------
__global__ void k_deg_init() {
    int i = blockIdx.x * blockDim.x + threadIdx.x;
    if (i < NN) g_deg[i] = 1;
}
__global__ void k_deg_count(const int* __restrict__ dst) {
    int e = blockIdx.x * blockDim.x + threadIdx.x;
    if (e < NE) atomicAdd(&g_deg[dst[e]], 1);
}
__global__ void k_dinv() {
    int i = blockIdx.x * blockDim.x + threadIdx.x;
    if (i < NN) {
        float d = (float)g_deg[i];
        g_dinv[i]   = rsqrtf(d);
        g_invdeg[i] = 1.0f / d;
    }
}

// ---------------- exclusive scan of in-degree -> row_ptr ----------------
__global__ void k_scan1() {
    __shared__ int sm[SCAN_B];
    int tid = threadIdx.x;
    int i = blockIdx.x * SCAN_B + tid;
    int v = (i < NN) ? (g_deg[i] - 1) : 0;
    sm[tid] = v;
    __syncthreads();
    for (int off = 1; off < SCAN_B; off <<= 1) {
        int t = (tid >= off) ? sm[tid - off] : 0;
        __syncthreads();
        sm[tid] += t;
        __syncthreads();
    }
    if (i < NN) g_rowptr[i] = sm[tid] - v;
    if (tid == SCAN_B - 1) g_bsums[blockIdx.x] = sm[tid];
}
__global__ void k_scan2() {
    __shared__ int sm[128];
    int tid = threadIdx.x;
    int v = (tid < NB_SCAN) ? g_bsums[tid] : 0;
    sm[tid] = v;
    __syncthreads();
    for (int off = 1; off < 128; off <<= 1) {
        int t = (tid >= off) ? sm[tid - off] : 0;
        __syncthreads();
        sm[tid] += t;
        __syncthreads();
    }
    if (tid < NB_SCAN) g_bsums[tid] = sm[tid] - v;
}
__global__ void k_scan3() {
    int i = blockIdx.x * blockDim.x + threadIdx.x;
    if (i < NN) {
        int r = g_rowptr[i] + g_bsums[i / SCAN_B];
        g_rowptr[i] = r;
        g_cursor[i] = r;
    }
    if (i == 0) g_rowptr[NN] = NE;
}
__global__ void k_edge_scatter(const int* __restrict__ src, const int* __restrict__ dst) {
    int e = blockIdx.x * blockDim.x + threadIdx.x;
    if (e < NE) {
        int s = src[e];
        int d = dst[e];
        int pos = atomicAdd(&g_cursor[d], 1);
        float norm = g_dinv[s] * g_dinv[d];
        g_edge[pos] = make_uint2((unsigned)s, __float_as_uint(norm));
    }
}

// ---------------- bf16 hi/lo split of input x ----------------
__global__ void k_split_x(const float* __restrict__ x) {
    int i = blockIdx.x * blockDim.x + threadIdx.x;   // handles 4 floats
    if (i >= NN * HF / 4) return;
    float4 v = ((const float4*)x)[i];
    __nv_bfloat16 h0 = __float2bfloat16(v.x), h1 = __float2bfloat16(v.y);
    __nv_bfloat16 h2 = __float2bfloat16(v.z), h3 = __float2bfloat16(v.w);
    __nv_bfloat16 l0 = __float2bfloat16(v.x - __bfloat162float(h0));
    __nv_bfloat16 l1 = __float2bfloat16(v.y - __bfloat162float(h1));
    __nv_bfloat16 l2 = __float2bfloat16(v.z - __bfloat162float(h2));
    __nv_bfloat16 l3 = __float2bfloat16(v.w - __bfloat162float(h3));
    __nv_bfloat162 H01; H01.x = h0; H01.y = h1;
    __nv_bfloat162 H23; H23.x = h2; H23.y = h3;
    __nv_bfloat162 L01; L01.x = l0; L01.y = l1;
    __nv_bfloat162 L23; L23.x = l2; L23.y = l3;
    ((__nv_bfloat162*)g_ahi)[2 * i]     = H01;
    ((__nv_bfloat162*)g_ahi)[2 * i + 1] = H23;
    ((__nv_bfloat162*)g_alo)[2 * i]     = L01;
    ((__nv_bfloat162*)g_alo)[2 * i + 1] = L23;
}

// ---------------- W^T hi/lo split (all 4 layers) ----------------
__global__ void k_wsplit(const float* __restrict__ W0, const float* __restrict__ W1,
                         const float* __restrict__ W2, const float* __restrict__ W3) {
    int i = blockIdx.x * blockDim.x + threadIdx.x;
    if (i >= 4 * HF * HF) return;
    int l = i >> 14;
    int rem = i & 16383;
    int n = rem >> 7;        // output col
    int k = rem & 127;       // input dim
    const float* W = (l == 0) ? W0 : (l == 1) ? W1 : (l == 2) ? W2 : W3;
    float v = W[k * HF + n];
    __nv_bfloat16 h = __float2bfloat16(v);
    __nv_bfloat16 lo = __float2bfloat16(v - __bfloat162float(h));
    g_wthi[i] = h;    // layout: [l][n][k]  (= col-major B for mma row.col)
    g_wtlo[i] = lo;
}

// ---------------- HMMA bf16x3 GEMM: g_h = (Ahi+Alo) @ (Whi+Wlo) ----------------
// 128x128x128 per CTA, 256 threads = 8 warps (2x4), warp tile 64x32.  (R9-proven)
__device__ __forceinline__ void fill_tile(char* smem, int off,
                                          const __nv_bfloat16* __restrict__ g,
                                          int row0, bool clampA, int tid) {
    const uint4* src = (const uint4*)g;
#pragma unroll
    for (int it = 0; it < 8; it++) {
        int idx = it * 256 + tid;       // 0..2047 (128 rows x 16 uint4)
        int row = idx >> 4;
        int seg = idx & 15;
        int grow = clampA ? min(row0 + row, NN - 1) : row;
        uint4 v = src[grow * 16 + seg];
        *(uint4*)(smem + off + row * (TSTR * 2) + seg * 16) = v;
    }
}

__global__ __launch_bounds__(256) void k_hgemm(int l) {
    extern __shared__ char smem[];
    const int tid  = threadIdx.x;
    const int warp = tid >> 5;
    const int lane = tid & 31;
    const int wm = warp >> 2;           // 0..1  (m block of 64)
    const int wn = warp & 3;            // 0..3  (n block of 32)
    const int row0 = blockIdx.x * 128;

    const __nv_bfloat16* Wh = g_wthi + l * HF * HF;
    const __nv_bfloat16* Wl = g_wtlo + l * HF * HF;
    fill_tile(smem, OFF_AHI, g_ahi, row0, true,  tid);
    fill_tile(smem, OFF_ALO, g_alo, row0, true,  tid);
    fill_tile(smem, OFF_BHI, Wh,    0,    false, tid);
    fill_tile(smem, OFF_BLO, Wl,    0,    false, tid);
    __syncthreads();

    const uint32_t sbase = smem_u32(smem);

    const int lgrp  = lane >> 3;        // 0..3
    const int lrow  = lane & 7;         // 0..7
    const int a_r   = (lgrp & 1) * 8 + lrow;
    const int a_k   = (lgrp >> 1) * 8;
    const int b_r   = lrow;
    const int b_k   = (lgrp & 1) * 8;

    float acc[4][4][4];
#pragma unroll
    for (int i = 0; i < 4; i++)
#pragma unroll
        for (int j = 0; j < 4; j++)
#pragma unroll
            for (int q = 0; q < 4; q++) acc[i][j][q] = 0.0f;

#pragma unroll
    for (int kc = 0; kc < 8; kc++) {
        uint32_t ahi[4][4], alo[4][4], bhi[4][2], blo[4][2];
#pragma unroll
        for (int mf = 0; mf < 4; mf++) {
            int mrow = wm * 64 + mf * 16 + a_r;
            uint32_t byteoff = (uint32_t)(mrow * (TSTR * 2) + (kc * 16 + a_k) * 2);
            ldsm_x4(ahi[mf], sbase + OFF_AHI + byteoff);
            ldsm_x4(alo[mf], sbase + OFF_ALO + byteoff);
        }
#pragma unroll
        for (int nf = 0; nf < 4; nf++) {
            int nrow = wn * 32 + nf * 8 + b_r;
            uint32_t byteoff = (uint32_t)(nrow * (TSTR * 2) + (kc * 16 + b_k) * 2);
            ldsm_x2(bhi[nf], sbase + OFF_BHI + byteoff);
            ldsm_x2(blo[nf], sbase + OFF_BLO + byteoff);
        }
#pragma unroll
        for (int mf = 0; mf < 4; mf++)
#pragma unroll
            for (int nf = 0; nf < 4; nf++) {
                mma_bf16(acc[mf][nf], ahi[mf], bhi[nf]);
                mma_bf16(acc[mf][nf], ahi[mf], blo[nf]);
                mma_bf16(acc[mf][nf], alo[mf], bhi[nf]);
            }
    }

    // epilogue: c frag lane l -> rows l/4 and l/4+8, cols (l%4)*2; store fp16 pairs
    const int crow = lane >> 2;
    const int ccol = (lane & 3) * 2;
#pragma unroll
    for (int mf = 0; mf < 4; mf++) {
        int r0 = row0 + wm * 64 + mf * 16 + crow;
        int r1 = r0 + 8;
#pragma unroll
        for (int nf = 0; nf < 4; nf++) {
            int c = wn * 32 + nf * 8 + ccol;
            if (r0 < NN)
                *(__half2*)&g_h[r0 * HF + c] = __floats2half2_rn(acc[mf][nf][0], acc[mf][nf][1]);
            if (r1 < NN)
                *(__half2*)&g_h[r1 * HF + c] = __floats2half2_rn(acc[mf][nf][2], acc[mf][nf][3]);
        }
    }
}

// ---------------- CSR gather aggregation + self-loop + bias + tanh ----------------
// One warp per node; TWO edges per warp-issue: lanes 0-15 = edge e (uint4 = 8 fp16
// features each), lanes 16-31 = edge e+1. Per edge-pair: 1 LDG.64 (packed meta)
// + 1 LDG.128 (gather). Cross-half merge via shfl_xor(16) at the end.
__device__ __forceinline__ void accum8(float* acc, uint4 hv, float w) {
    const __half2* hp = (const __half2*)&hv;
#pragma unroll
    for (int j = 0; j < 4; j++) {
        float2 f = __half22float2(hp[j]);
        acc[2 * j]     += w * f.x;
        acc[2 * j + 1] += w * f.y;
    }
}

__global__ __launch_bounds__(256) void k_agg(const float* __restrict__ bias, int last) {
    int node = blockIdx.x * 8 + (threadIdx.x >> 5);
    if (node >= NN) return;
    const int lane = threadIdx.x & 31;
    const int half = lane >> 4;         // 0: even edge, 1: odd edge
    const int fl   = lane & 15;         // feature chunk (8 fp16 = uint4)
    const uint4* __restrict__ hrow = (const uint4*)g_h;   // row stride = 16 uint4

    int beg = g_rowptr[node];
    int end = g_rowptr[node + 1];

    float acc[8];
#pragma unroll
    for (int j = 0; j < 8; j++) acc[j] = 0.0f;

    int e = beg;
    for (; e + 7 < end; e += 8) {       // 4 pairs = 8 edges
        uint2 m[4];
#pragma unroll
        for (int p = 0; p < 4; p++) m[p] = g_edge[e + 2 * p + half];
        uint4 hv[4];
#pragma unroll
        for (int p = 0; p < 4; p++) hv[p] = hrow[m[p].x * 16 + fl];
#pragma unroll
        for (int p = 0; p < 4; p++) accum8(acc, hv[p], __uint_as_float(m[p].y));
    }
    for (; e < end; e += 2) {           // pair tail, clamp second half
        int idx = e + half;
        bool valid = idx < end;
        uint2 m = g_edge[valid ? idx : (end - 1)];
        float w = valid ? __uint_as_float(m.y) : 0.0f;
        uint4 hv = hrow[m.x * 16 + fl];
        accum8(acc, hv, w);
    }

    // merge the two half-warp partial sums (same feature chunks, different edges)
#pragma unroll
    for (int j = 0; j < 8; j++) acc[j] += __shfl_xor_sync(0xffffffffu, acc[j], 16);

    // self-loop + bias + tanh
    uint4 sv = hrow[node * 16 + fl];
    float sf[8];
    {
        const __half2* hp = (const __half2*)&sv;
#pragma unroll
        for (int j = 0; j < 4; j++) {
            float2 f = __half22float2(hp[j]);
            sf[2 * j] = f.x; sf[2 * j + 1] = f.y;
        }
    }
    float inv = g_invdeg[node];
    const float4* b4 = (const float4*)bias;
    float4 bb0 = b4[fl * 2], bb1 = b4[fl * 2 + 1];
    float o[8];
    o[0] = tanhf(acc[0] + inv * sf[0] + bb0.x);
    o[1] = tanhf(acc[1] + inv * sf[1] + bb0.y);
    o[2] = tanhf(acc[2] + inv * sf[2] + bb0.z);
    o[3] = tanhf(acc[3] + inv * sf[3] + bb0.w);
    o[4] = tanhf(acc[4] + inv * sf[4] + bb1.x);
    o[5] = tanhf(acc[5] + inv * sf[5] + bb1.y);
    o[6] = tanhf(acc[6] + inv * sf[6] + bb1.z);
    o[7] = tanhf(acc[7] + inv * sf[7] + bb1.w);

    if (half == 0) {                    // lanes 0-15 write (both halves hold identical o[])
        if (last) {
            float4* dst = (float4*)&g_xB[node * HF + fl * 8];
            dst[0] = make_float4(o[0], o[1], o[2], o[3]);
            dst[1] = make_float4(o[4], o[5], o[6], o[7]);
        } else {
            uint32_t hi[4], lo[4];
#pragma unroll
            for (int j = 0; j < 4; j++) {
                float a = o[2 * j], b = o[2 * j + 1];
                __nv_bfloat16 ha = __float2bfloat16(a), hb = __float2bfloat16(b);
                __nv_bfloat16 la = __float2bfloat16(a - __bfloat162float(ha));
                __nv_bfloat16 lb = __float2bfloat16(b - __bfloat162float(hb));
                __nv_bfloat162 H; H.x = ha; H.y = hb;
                __nv_bfloat162 L; L.x = la; L.y = lb;
                hi[j] = *(uint32_t*)&H;
                lo[j] = *(uint32_t*)&L;
            }
            ((uint4*)g_ahi)[node * 16 + fl] = make_uint4(hi[0], hi[1], hi[2], hi[3]);
            ((uint4*)g_alo)[node * 16 + fl] = make_uint4(lo[0], lo[1], lo[2], lo[3]);
        }
    }
}

// ---------------- pooling ----------------
__global__ void k_pool_init() {
    int i = blockIdx.x * blockDim.x + threadIdx.x;
    if (i < NG * HF) {
        g_gmax[i] = -INFINITY;
        g_gsum[i] = 0.0f;
    }
    if (i < NG) g_gcnt[i] = 0;
}

__device__ __forceinline__ void atomicMaxF(float* addr, float v) {
    if (v >= 0.0f) atomicMax((int*)addr, __float_as_int(v));
    else           atomicMin((unsigned int*)addr, __float_as_uint(v));
}

__global__ __launch_bounds__(128) void k_pool(const int* __restrict__ batch) {
    const float* __restrict__ x = g_xB;
    int t  = threadIdx.x;
    int n0 = blockIdx.x * POOL_CH;
    if (n0 >= NN) return;
    int n1 = min(n0 + POOL_CH, NN);

    int cur = -1;
    float rmax = -INFINITY, rsum = 0.0f;
    int rcnt = 0;
    for (int n = n0; n < n1; n++) {
        int g = batch[n];
        if (g != cur) {
            if (cur >= 0) {
                atomicMaxF(&g_gmax[cur * HF + t], rmax);
                atomicAdd(&g_gsum[cur * HF + t], rsum);
                if (t == 0) atomicAdd(&g_gcnt[cur], rcnt);
            }
            cur = g; rmax = -INFINITY; rsum = 0.0f; rcnt = 0;
        }
        float v = x[n * HF + t];
        rmax = fmaxf(rmax, v);
        rsum += v;
        rcnt++;
    }
    if (cur >= 0) {
        atomicMaxF(&g_gmax[cur * HF + t], rmax);
        atomicAdd(&g_gsum[cur * HF + t], rsum);
        if (t == 0) atomicAdd(&g_gcnt[cur], rcnt);
    }
}

// ---------------- finalize ----------------
__global__ __launch_bounds__(256) void k_finalize(const float* __restrict__ Wout,
                                                  const float* __restrict__ bout,
                                                  float* __restrict__ dout, int out_size) {
    __shared__ float p[2 * HF];
    int g = blockIdx.x;
    int t = threadIdx.x;

    float val;
    if (t < HF) {
        val = g_gmax[g * HF + t];
    } else {
        float c = fmaxf((float)g_gcnt[g], 1.0f);
        val = g_gsum[g * HF + (t - HF)] / c;
    }
    p[t] = val;
    int pidx = NG * NC + g * (2 * HF) + t;
    if (pidx < out_size) dout[pidx] = val;
    __syncthreads();

    if (t < NC) {
        float s = bout[t];
#pragma unroll 8
        for (int j = 0; j < 2 * HF; j++) s += p[j] * Wout[j * NC + t];
        int oidx = g * NC + t;
        if (oidx < out_size) dout[oidx] = s;
    }
}

// ---------------- launch ----------------
extern "C" void kernel_launch(void* const* d_in, const int* in_sizes, int n_in,
                              void* d_out, int out_size) {
    const float* x     = (const float*)d_in[0];
    const int*   ei    = (const int*)  d_in[1];
    const int*   batch = (const int*)  d_in[2];
    const float* W0 = (const float*)d_in[3];  const float* b0 = (const float*)d_in[4];
    const float* W1 = (const float*)d_in[5];  const float* b1 = (const float*)d_in[6];
    const float* W2 = (const float*)d_in[7];  const float* b2 = (const float*)d_in[8];
    const float* W3 = (const float*)d_in[9];  const float* b3 = (const float*)d_in[10];
    const float* Wout = (const float*)d_in[11];
    const float* bout = (const float*)d_in[12];
    float* dout = (float*)d_out;

    const int* src = ei;
    const int* dst = ei + NE;

    const int TB = 256;
    const int gN = (NN + TB - 1) / TB;
    const int gE = (NE + TB - 1) / TB;
    const int gGemm = (NN + 127) / 128;       // 782
    const int gAgg  = (NN + 7) / 8;
    const int gPool = (NN + POOL_CH - 1) / POOL_CH;

    // Idempotent, capture-safe (not a stream op).
    cudaFuncSetAttribute(k_hgemm, cudaFuncAttributeMaxDynamicSharedMemorySize, SMB);

    // ---- graph preprocessing ----
    k_deg_init<<<gN, TB>>>();
    k_deg_count<<<gE, TB>>>(dst);
    k_dinv<<<gN, TB>>>();
    k_scan1<<<NB_SCAN, SCAN_B>>>();
    k_scan2<<<1, 128>>>();
    k_scan3<<<gN, TB>>>();
    k_edge_scatter<<<gE, TB>>>(src, dst);

    // ---- precision splits ----
    k_split_x<<<(NN * HF / 4 + TB - 1) / TB, TB>>>(x);
    k_wsplit<<<(4 * HF * HF + TB - 1) / TB, TB>>>(W0, W1, W2, W3);

    // ---- 4 GCN layers ----
    const float* biases[4] = {b0, b1, b2, b3};
    for (int l = 0; l < 4; l++) {
        k_hgemm<<<gGemm, 256, SMB>>>(l);
        k_agg<<<gAgg, 256>>>(biases[l], l == 3 ? 1 : 0);
    }

    // ---- pooling + head ----
    k_pool_init<<<(NG * HF + TB - 1) / TB, TB>>>();
    k_pool<<<gPool, 128>>>(batch);
    k_finalize<<<NG, 256>>>(Wout, bout, dout, out_size);
}

// round 13
// speedup vs baseline: 1.1977x; 1.1977x over previous
#include <cuda_runtime.h>
#include <cuda_bf16.h>
#include <cuda_fp16.h>
#include <cstdint>
#include <math.h>

#define NN 100000
#define NE 1600000
#define HF 128
#define NG 64
#define NC 10
#define SCAN_B 1024
#define NB_SCAN ((NN + SCAN_B - 1) / SCAN_B)   // 98
#define POOL_CH 256

// GEMM smem tile geometry: 128 rows x 128 fp16, padded stride 136 elems (272B)
#define TSTR 136
#define TILE_BYTES (128 * TSTR * 2)            // 34816
#define OFF_A   0
#define OFF_BHI (TILE_BYTES)
#define OFF_BLO (2 * TILE_BYTES)
#define SMB     (3 * TILE_BYTES)               // 104448 -> 2 CTA/SM

// ---------------- scratch (static device globals; no allocation) ----------------
__device__ __half g_h  [NN * HF];             // GEMM output per layer (fp16 rows, 256B)
__device__ __half g_ax [NN * HF];             // activation (GEMM A input, fp16)
__device__ __half g_whi[4 * HF * HF];         // W^T hi per layer, layout [l][n][k]
__device__ __half g_wlo[4 * HF * HF];         // W^T lo per layer
__device__ float g_xB [NN * HF];              // final layer fp32 output (for pooling)
__device__ int   g_deg   [NN];
__device__ float g_dinv  [NN];
__device__ float g_invdeg[NN];
__device__ int   g_rowptr[NN + 1];
__device__ int   g_cursor[NN];
__device__ uint2 g_edge  [NE];                // packed {src, norm_bits}
__device__ int   g_bsums [128];
__device__ float g_gmax  [NG * HF];
__device__ float g_gsum  [NG * HF];
__device__ int   g_gcnt  [NG];

// ================= mma.sync / ldmatrix helpers (arch-portable PTX) =================
__device__ __forceinline__ uint32_t smem_u32(const void* p) {
    uint32_t a;
    asm("{ .reg .u64 t; cvta.to.shared.u64 t, %1; cvt.u32.u64 %0, t; }" : "=r"(a) : "l"(p));
    return a;
}
__device__ __forceinline__ void ldsm_x4(uint32_t* r, uint32_t addr) {
    asm volatile("ldmatrix.sync.aligned.m8n8.x4.shared.b16 {%0,%1,%2,%3}, [%4];"
        : "=r"(r[0]), "=r"(r[1]), "=r"(r[2]), "=r"(r[3]) : "r"(addr));
}
__device__ __forceinline__ void ldsm_x2(uint32_t* r, uint32_t addr) {
    asm volatile("ldmatrix.sync.aligned.m8n8.x2.shared.b16 {%0,%1}, [%2];"
        : "=r"(r[0]), "=r"(r[1]) : "r"(addr));
}
__device__ __forceinline__ void mma_f16(float* c, const uint32_t* a, const uint32_t* b) {
    asm volatile("mma.sync.aligned.m16n8k16.row.col.f32.f16.f16.f32 "
        "{%0,%1,%2,%3}, {%4,%5,%6,%7}, {%8,%9}, {%0,%1,%2,%3};"
        : "+f"(c[0]), "+f"(c[1]), "+f"(c[2]), "+f"(c[3])
        : "r"(a[0]), "r"(a[1]), "r"(a[2]), "r"(a[3]), "r"(b[0]), "r"(b[1]));
}

// ---------------- degree / normalization ----------------
__global__ void k_deg_init() {
    int i = blockIdx.x * blockDim.x + threadIdx.x;
    if (i < NN) g_deg[i] = 1;
}
__global__ void k_deg_count(const int* __restrict__ dst) {
    int e = blockIdx.x * blockDim.x + threadIdx.x;
    if (e < NE) atomicAdd(&g_deg[dst[e]], 1);
}
__global__ void k_dinv() {
    int i = blockIdx.x * blockDim.x + threadIdx.x;
    if (i < NN) {
        float d = (float)g_deg[i];
        g_dinv[i]   = rsqrtf(d);
        g_invdeg[i] = 1.0f / d;
    }
}

// ---------------- exclusive scan of in-degree -> row_ptr ----------------
__global__ void k_scan1() {
    __shared__ int sm[SCAN_B];
    int tid = threadIdx.x;
    int i = blockIdx.x * SCAN_B + tid;
    int v = (i < NN) ? (g_deg[i] - 1) : 0;
    sm[tid] = v;
    __syncthreads();
    for (int off = 1; off < SCAN_B; off <<= 1) {
        int t = (tid >= off) ? sm[tid - off] : 0;
        __syncthreads();
        sm[tid] += t;
        __syncthreads();
    }
    if (i < NN) g_rowptr[i] = sm[tid] - v;
    if (tid == SCAN_B - 1) g_bsums[blockIdx.x] = sm[tid];
}
__global__ void k_scan2() {
    __shared__ int sm[128];
    int tid = threadIdx.x;
    int v = (tid < NB_SCAN) ? g_bsums[tid] : 0;
    sm[tid] = v;
    __syncthreads();
    for (int off = 1; off < 128; off <<= 1) {
        int t = (tid >= off) ? sm[tid - off] : 0;
        __syncthreads();
        sm[tid] += t;
        __syncthreads();
    }
    if (tid < NB_SCAN) g_bsums[tid] = sm[tid] - v;
}
__global__ void k_scan3() {
    int i = blockIdx.x * blockDim.x + threadIdx.x;
    if (i < NN) {
        int r = g_rowptr[i] + g_bsums[i / SCAN_B];
        g_rowptr[i] = r;
        g_cursor[i] = r;
    }
    if (i == 0) g_rowptr[NN] = NE;
}
__global__ void k_edge_scatter(const int* __restrict__ src, const int* __restrict__ dst) {
    int e = blockIdx.x * blockDim.x + threadIdx.x;
    if (e < NE) {
        int s = src[e];
        int d = dst[e];
        int pos = atomicAdd(&g_cursor[d], 1);
        float norm = g_dinv[s] * g_dinv[d];
        g_edge[pos] = make_uint2((unsigned)s, __float_as_uint(norm));
    }
}

// ---------------- x -> fp16 A ----------------
__global__ void k_split_x(const float* __restrict__ x) {
    int i = blockIdx.x * blockDim.x + threadIdx.x;   // handles 4 floats
    if (i >= NN * HF / 4) return;
    float4 v = ((const float4*)x)[i];
    __half2 a = __floats2half2_rn(v.x, v.y);
    __half2 b = __floats2half2_rn(v.z, v.w);
    ((uint2*)g_ax)[i] = make_uint2(*(uint32_t*)&a, *(uint32_t*)&b);
}

// ---------------- W^T fp16 hi/lo split (all 4 layers) ----------------
__global__ void k_wsplit(const float* __restrict__ W0, const float* __restrict__ W1,
                         const float* __restrict__ W2, const float* __restrict__ W3) {
    int i = blockIdx.x * blockDim.x + threadIdx.x;
    if (i >= 4 * HF * HF) return;
    int l = i >> 14;
    int rem = i & 16383;
    int n = rem >> 7;        // output col
    int k = rem & 127;       // input dim
    const float* W = (l == 0) ? W0 : (l == 1) ? W1 : (l == 2) ? W2 : W3;
    float v = W[k * HF + n];
    __half h = __float2half_rn(v);
    __half lo = __float2half_rn(v - __half2float(h));
    g_whi[i] = h;    // layout: [l][n][k]  (= col-major B for mma row.col)
    g_wlo[i] = lo;
}

// ---------------- HMMA fp16x2 GEMM: g_h = A @ (Whi + Wlo) ----------------
// 128x128x128 per CTA (2 CTA/SM), 256 threads = 8 warps (2x4), warp tile 64x32.
__device__ __forceinline__ void fill_tile(char* smem, int off,
                                          const void* __restrict__ g,
                                          int row0, bool clampA, int tid) {
    const uint4* src = (const uint4*)g;
#pragma unroll
    for (int it = 0; it < 8; it++) {
        int idx = it * 256 + tid;       // 0..2047 (128 rows x 16 uint4)
        int row = idx >> 4;
        int seg = idx & 15;
        int grow = clampA ? min(row0 + row, NN - 1) : row;
        uint4 v = src[grow * 16 + seg];
        *(uint4*)(smem + off + row * (TSTR * 2) + seg * 16) = v;
    }
}

__global__ __launch_bounds__(256) void k_hgemm(int l) {
    extern __shared__ char smem[];
    const int tid  = threadIdx.x;
    const int warp = tid >> 5;
    const int lane = tid & 31;
    const int wm = warp >> 2;           // 0..1  (m block of 64)
    const int wn = warp & 3;            // 0..3  (n block of 32)
    const int row0 = blockIdx.x * 128;

    fill_tile(smem, OFF_A,   g_ax,              row0, true,  tid);
    fill_tile(smem, OFF_BHI, g_whi + l * HF * HF, 0,  false, tid);
    fill_tile(smem, OFF_BLO, g_wlo + l * HF * HF, 0,  false, tid);
    __syncthreads();

    const uint32_t sbase = smem_u32(smem);

    const int lgrp  = lane >> 3;        // 0..3
    const int lrow  = lane & 7;         // 0..7
    const int a_r   = (lgrp & 1) * 8 + lrow;
    const int a_k   = (lgrp >> 1) * 8;
    const int b_r   = lrow;
    const int b_k   = (lgrp & 1) * 8;

    float acc[4][4][4];
#pragma unroll
    for (int i = 0; i < 4; i++)
#pragma unroll
        for (int j = 0; j < 4; j++)
#pragma unroll
            for (int q = 0; q < 4; q++) acc[i][j][q] = 0.0f;

#pragma unroll
    for (int kc = 0; kc < 8; kc++) {
        uint32_t af[4][4], bhi[4][2], blo[4][2];
#pragma unroll
        for (int mf = 0; mf < 4; mf++) {
            int mrow = wm * 64 + mf * 16 + a_r;
            uint32_t byteoff = (uint32_t)(mrow * (TSTR * 2) + (kc * 16 + a_k) * 2);
            ldsm_x4(af[mf], sbase + OFF_A + byteoff);
        }
#pragma unroll
        for (int nf = 0; nf < 4; nf++) {
            int nrow = wn * 32 + nf * 8 + b_r;
            uint32_t byteoff = (uint32_t)(nrow * (TSTR * 2) + (kc * 16 + b_k) * 2);
            ldsm_x2(bhi[nf], sbase + OFF_BHI + byteoff);
            ldsm_x2(blo[nf], sbase + OFF_BLO + byteoff);
        }
#pragma unroll
        for (int mf = 0; mf < 4; mf++)
#pragma unroll
            for (int nf = 0; nf < 4; nf++) {
                mma_f16(acc[mf][nf], af[mf], bhi[nf]);
                mma_f16(acc[mf][nf], af[mf], blo[nf]);
            }
    }

    // epilogue: c frag lane l -> rows l/4 and l/4+8, cols (l%4)*2; store fp16 pairs
    const int crow = lane >> 2;
    const int ccol = (lane & 3) * 2;
#pragma unroll
    for (int mf = 0; mf < 4; mf++) {
        int r0 = row0 + wm * 64 + mf * 16 + crow;
        int r1 = r0 + 8;
#pragma unroll
        for (int nf = 0; nf < 4; nf++) {
            int c = wn * 32 + nf * 8 + ccol;
            if (r0 < NN)
                *(__half2*)&g_h[r0 * HF + c] = __floats2half2_rn(acc[mf][nf][0], acc[mf][nf][1]);
            if (r1 < NN)
                *(__half2*)&g_h[r1 * HF + c] = __floats2half2_rn(acc[mf][nf][2], acc[mf][nf][3]);
        }
    }
}

// ---------------- CSR gather aggregation + self-loop + bias + tanh ----------------
// one warp per node, lane owns 4 features (one uint2 = 4 fp16); unroll-4 (R11-proven).
// Writes fp16 g_ax (next GEMM A) except last layer (fp32 for pooling).
__device__ __forceinline__ float4 h4_from_u2(uint2 u) {
    __half2 p0 = *(__half2*)&u.x;
    __half2 p1 = *(__half2*)&u.y;
    float2 f0 = __half22float2(p0);
    float2 f1 = __half22float2(p1);
    return make_float4(f0.x, f0.y, f1.x, f1.y);
}

__global__ __launch_bounds__(256) void k_agg(const float* __restrict__ bias, int last) {
    int node = blockIdx.x * 8 + (threadIdx.x >> 5);
    if (node >= NN) return;
    int lane = threadIdx.x & 31;
    const uint2* __restrict__ h2 = (const uint2*)g_h;   // row = 32 uint2

    int beg = g_rowptr[node];
    int end = g_rowptr[node + 1];

    float4 acc = make_float4(0.f, 0.f, 0.f, 0.f);
    int e = beg;
    for (; e + 3 < end; e += 4) {
        uint2 m0 = g_edge[e],     m1 = g_edge[e + 1];
        uint2 m2 = g_edge[e + 2], m3 = g_edge[e + 3];
        float4 v0 = h4_from_u2(h2[m0.x * 32 + lane]);
        float4 v1 = h4_from_u2(h2[m1.x * 32 + lane]);
        float4 v2 = h4_from_u2(h2[m2.x * 32 + lane]);
        float4 v3 = h4_from_u2(h2[m3.x * 32 + lane]);
        float w0 = __uint_as_float(m0.y), w1 = __uint_as_float(m1.y);
        float w2 = __uint_as_float(m2.y), w3 = __uint_as_float(m3.y);
        acc.x += w0 * v0.x + w1 * v1.x + w2 * v2.x + w3 * v3.x;
        acc.y += w0 * v0.y + w1 * v1.y + w2 * v2.y + w3 * v3.y;
        acc.z += w0 * v0.z + w1 * v1.z + w2 * v2.z + w3 * v3.z;
        acc.w += w0 * v0.w + w1 * v1.w + w2 * v2.w + w3 * v3.w;
    }
    for (; e < end; e++) {
        uint2 m = g_edge[e];
        float w = __uint_as_float(m.y);
        float4 v = h4_from_u2(h2[m.x * 32 + lane]);
        acc.x += w * v.x; acc.y += w * v.y; acc.z += w * v.z; acc.w += w * v.w;
    }

    float4 hs = h4_from_u2(h2[node * 32 + lane]);
    float inv = g_invdeg[node];
    float4 bb = ((const float4*)bias)[lane];
    float4 o;
    o.x = tanhf(acc.x + inv * hs.x + bb.x);
    o.y = tanhf(acc.y + inv * hs.y + bb.y);
    o.z = tanhf(acc.z + inv * hs.z + bb.z);
    o.w = tanhf(acc.w + inv * hs.w + bb.w);

    if (last) {
        ((float4*)g_xB)[node * 32 + lane] = o;
    } else {
        __half2 a = __floats2half2_rn(o.x, o.y);
        __half2 b = __floats2half2_rn(o.z, o.w);
        ((uint2*)g_ax)[node * 32 + lane] = make_uint2(*(uint32_t*)&a, *(uint32_t*)&b);
    }
}

// ---------------- pooling ----------------
__global__ void k_pool_init() {
    int i = blockIdx.x * blockDim.x + threadIdx.x;
    if (i < NG * HF) {
        g_gmax[i] = -INFINITY;
        g_gsum[i] = 0.0f;
    }
    if (i < NG) g_gcnt[i] = 0;
}

__device__ __forceinline__ void atomicMaxF(float* addr, float v) {
    if (v >= 0.0f) atomicMax((int*)addr, __float_as_int(v));
    else           atomicMin((unsigned int*)addr, __float_as_uint(v));
}

__global__ __launch_bounds__(128) void k_pool(const int* __restrict__ batch) {
    const float* __restrict__ x = g_xB;
    int t  = threadIdx.x;
    int n0 = blockIdx.x * POOL_CH;
    if (n0 >= NN) return;
    int n1 = min(n0 + POOL_CH, NN);

    int cur = -1;
    float rmax = -INFINITY, rsum = 0.0f;
    int rcnt = 0;
    for (int n = n0; n < n1; n++) {
        int g = batch[n];
        if (g != cur) {
            if (cur >= 0) {
                atomicMaxF(&g_gmax[cur * HF + t], rmax);
                atomicAdd(&g_gsum[cur * HF + t], rsum);
                if (t == 0) atomicAdd(&g_gcnt[cur], rcnt);
            }
            cur = g; rmax = -INFINITY; rsum = 0.0f; rcnt = 0;
        }
        float v = x[n * HF + t];
        rmax = fmaxf(rmax, v);
        rsum += v;
        rcnt++;
    }
    if (cur >= 0) {
        atomicMaxF(&g_gmax[cur * HF + t], rmax);
        atomicAdd(&g_gsum[cur * HF + t], rsum);
        if (t == 0) atomicAdd(&g_gcnt[cur], rcnt);
    }
}

// ---------------- finalize ----------------
__global__ __launch_bounds__(256) void k_finalize(const float* __restrict__ Wout,
                                                  const float* __restrict__ bout,
                                                  float* __restrict__ dout, int out_size) {
    __shared__ float p[2 * HF];
    int g = blockIdx.x;
    int t = threadIdx.x;

    float val;
    if (t < HF) {
        val = g_gmax[g * HF + t];
    } else {
        float c = fmaxf((float)g_gcnt[g], 1.0f);
        val = g_gsum[g * HF + (t - HF)] / c;
    }
    p[t] = val;
    int pidx = NG * NC + g * (2 * HF) + t;
    if (pidx < out_size) dout[pidx] = val;
    __syncthreads();

    if (t < NC) {
        float s = bout[t];
#pragma unroll 8
        for (int j = 0; j < 2 * HF; j++) s += p[j] * Wout[j * NC + t];
        int oidx = g * NC + t;
        if (oidx < out_size) dout[oidx] = s;
    }
}

// ---------------- launch ----------------
extern "C" void kernel_launch(void* const* d_in, const int* in_sizes, int n_in,
                              void* d_out, int out_size) {
    const float* x     = (const float*)d_in[0];
    const int*   ei    = (const int*)  d_in[1];
    const int*   batch = (const int*)  d_in[2];
    const float* W0 = (const float*)d_in[3];  const float* b0 = (const float*)d_in[4];
    const float* W1 = (const float*)d_in[5];  const float* b1 = (const float*)d_in[6];
    const float* W2 = (const float*)d_in[7];  const float* b2 = (const float*)d_in[8];
    const float* W3 = (const float*)d_in[9];  const float* b3 = (const float*)d_in[10];
    const float* Wout = (const float*)d_in[11];
    const float* bout = (const float*)d_in[12];
    float* dout = (float*)d_out;

    const int* src = ei;
    const int* dst = ei + NE;

    const int TB = 256;
    const int gN = (NN + TB - 1) / TB;
    const int gE = (NE + TB - 1) / TB;
    const int gGemm = (NN + 127) / 128;       // 782
    const int gAgg  = (NN + 7) / 8;
    const int gPool = (NN + POOL_CH - 1) / POOL_CH;

    // Idempotent, capture-safe (not a stream op).
    cudaFuncSetAttribute(k_hgemm, cudaFuncAttributeMaxDynamicSharedMemorySize, SMB);

    // ---- graph preprocessing ----
    k_deg_init<<<gN, TB>>>();
    k_deg_count<<<gE, TB>>>(dst);
    k_dinv<<<gN, TB>>>();
    k_scan1<<<NB_SCAN, SCAN_B>>>();
    k_scan2<<<1, 128>>>();
    k_scan3<<<gN, TB>>>();
    k_edge_scatter<<<gE, TB>>>(src, dst);

    // ---- precision prep ----
    k_split_x<<<(NN * HF / 4 + TB - 1) / TB, TB>>>(x);
    k_wsplit<<<(4 * HF * HF + TB - 1) / TB, TB>>>(W0, W1, W2, W3);

    // ---- 4 GCN layers ----
    const float* biases[4] = {b0, b1, b2, b3};
    for (int l = 0; l < 4; l++) {
        k_hgemm<<<gGemm, 256, SMB>>>(l);
        k_agg<<<gAgg, 256>>>(biases[l], l == 3 ? 1 : 0);
    }

    // ---- pooling + head ----
    k_pool_init<<<(NG * HF + TB - 1) / TB, TB>>>();
    k_pool<<<gPool, 128>>>(batch);
    k_finalize<<<NG, 256>>>(Wout, bout, dout, out_size);
}